// round 1
// baseline (speedup 1.0000x reference)
#include <cuda_runtime.h>
#include <cuda_bf16.h>
#include <cstdint>

// DTW wavefront, single persistent CTA.
// N=65536 rows (input), K=512 cols (kernel). Thread j owns column j.
// Skewed blocking: R=8 rows per macro-step, thread j at step t computes
// rows [R*(t-j), R*(t-j)+R). Left/diag values come from thread j-1's
// outputs of the previous step (shfl_up within a warp, smem across warps).

#define KLEN 512
#define RROWS 8
#define NWARPS 16

__device__ __forceinline__ float inf_f() { return __int_as_float(0x7f800000); }

__global__ void __launch_bounds__(KLEN, 1)
dtw_wavefront_kernel(const float* __restrict__ x,
                     const float* __restrict__ ker,
                     float* __restrict__ out,
                     int N)
{
    const int j    = threadIdx.x;       // column index
    const int lane = j & 31;
    const int w    = j >> 5;
    const int NB   = N / RROWS;         // row-blocks per column (8192)
    const int STEPS = NB + (KLEN - 1);

    const float kj = __ldg(&ker[j]);
    const float INFV = inf_f();

    // double-buffered cross-warp boundary: lane31 of warp w -> lane0 of warp w+1
    __shared__ float sbuf[2][NWARPS][RROWS];

    // DP carries
    float uc     = (j == 0) ? 0.0f : INFV;  // ac[prev_row][j] carry ("up" for first row of block)
    float dcarry = INFV;                    // ac[prev_row][j-1] carry ("diag" for first row of block)
    float ac[RROWS];                        // this thread's outputs of the current/previous step
    #pragma unroll
    for (int r = 0; r < RROWS; ++r) ac[r] = INFV;

    // software-pipelined x loads (next block staged in registers)
    float4 xA = make_float4(0.f,0.f,0.f,0.f);
    float4 xB = make_float4(0.f,0.f,0.f,0.f);

    for (int t = 0; t < STEPS; ++t) {
        const int  b      = t - j;
        const bool active = (b >= 0) && (b < NB);

        // ---- 1. gather left-neighbor values (neighbor's outputs from step t-1) ----
        float left[RROWS];
        #pragma unroll
        for (int r = 0; r < RROWS; ++r)
            left[r] = __shfl_up_sync(0xffffffffu, ac[r], 1);
        if (lane == 0) {
            if (w == 0) {
                #pragma unroll
                for (int r = 0; r < RROWS; ++r) left[r] = INFV;   // column 0 has no left neighbor
            } else {
                #pragma unroll
                for (int r = 0; r < RROWS; ++r) left[r] = sbuf[(t + 1) & 1][w - 1][r];
            }
        }

        if (active) {
            // ---- 2. x values for this block (from last step's prefetch) ----
            float xv[RROWS];
            if (b == 0) {
                const float4* p = reinterpret_cast<const float4*>(x);
                float4 a = __ldg(p + 0);
                float4 c = __ldg(p + 1);
                xv[0]=a.x; xv[1]=a.y; xv[2]=a.z; xv[3]=a.w;
                xv[4]=c.x; xv[5]=c.y; xv[6]=c.z; xv[7]=c.w;
            } else {
                xv[0]=xA.x; xv[1]=xA.y; xv[2]=xA.z; xv[3]=xA.w;
                xv[4]=xB.x; xv[5]=xB.y; xv[6]=xB.z; xv[7]=xB.w;
            }
            // prefetch next block into registers
            const int nb = b + 1;
            if (nb < NB) {
                const float4* p = reinterpret_cast<const float4*>(x + nb * RROWS);
                xA = __ldg(p + 0);
                xB = __ldg(p + 1);
            }
            // lead thread warms L2 well ahead of the wavefront head (hide DRAM 577cyc)
            if (j == 0) {
                const int pb = b + 6;
                if (pb < NB)
                    asm volatile("prefetch.global.L2 [%0];" :: "l"(x + pb * RROWS));
            }

            // ---- 3. squared distances (off critical chain) ----
            float dsq[RROWS];
            #pragma unroll
            for (int r = 0; r < RROWS; ++r) {
                const float diff = kj - xv[r];
                dsq[r] = diff * diff;
            }

            // ---- 4. DP cells: ac[r] = min(diag, left, up) + d ----
            float diag = dcarry;
            float up   = uc;
            #pragma unroll
            for (int r = 0; r < RROWS; ++r) {
                const float e = fminf(diag, left[r]);   // off-chain
                const float v = fminf(e, up) + dsq[r];  // chain: FMNMX + FADD
                ac[r] = v;
                up    = v;
                diag  = left[r];
            }
            uc     = up;
            dcarry = left[RROWS - 1];

            // ---- 5. last column emits outputs ----
            if (j == KLEN - 1) {
                #pragma unroll
                for (int r = 0; r < RROWS; ++r)
                    out[b * RROWS + r] = ac[r];
            }
        }

        // ---- 6. publish warp boundary for next step ----
        if (lane == 31 && w < NWARPS - 1) {
            #pragma unroll
            for (int r = 0; r < RROWS; ++r)
                sbuf[t & 1][w][r] = ac[r];
        }
        __syncthreads();
    }
}

extern "C" void kernel_launch(void* const* d_in, const int* in_sizes, int n_in,
                              void* d_out, int out_size)
{
    // inputs per metadata: [0]=input (65536 f32), [1]=kernel (512 f32).
    // Identify robustly by size.
    const float* x;
    const float* ker;
    int N;
    if (n_in >= 2 && in_sizes[0] == KLEN && in_sizes[1] != KLEN) {
        ker = (const float*)d_in[0];
        x   = (const float*)d_in[1];
        N   = in_sizes[1];
    } else {
        x   = (const float*)d_in[0];
        ker = (const float*)d_in[1];
        N   = in_sizes[0];
    }
    float* out = (float*)d_out;

    dtw_wavefront_kernel<<<1, KLEN>>>(x, ker, out, N);
}

// round 2
// speedup vs baseline: 1.4429x; 1.4429x over previous
#include <cuda_runtime.h>
#include <cuda_bf16.h>
#include <cstdint>

// DTW wavefront across 16 SMs.
// K=512 columns split as 16 CTAs x 32 lanes (one column per lane, one CTA per SM).
// Each lane walks its column in blocks of R=16 rows. Intra-CTA left/diag deps via
// shfl_up; inter-CTA deps via a device-global boundary array + monotonic
// release/acquire progress flag (decoupled-lookback style).
//
// Min-plus scan form per block (halves dependent chain):
//   e[r] = min(diag[r], left[r])          (off-chain)
//   m[r] = min(m[r-1], e[r] - S[r-1])     (chain: 1 FMNMX / cell)
//   v[r] = m[r] + S[r],  S = prefix sum of d, m[-1] = up-carry.

#define KLEN  512
#define RR    16
#define NCTA  16
#define NBMAX 4096   // 65536 / 16

__device__ float    g_bnd[NCTA][NBMAX][RR];   // boundary (col 32w+31) values per block
__device__ unsigned g_flag[NCTA];             // blocks published by CTA w (monotonic per run)

__device__ __forceinline__ unsigned ld_acq(const unsigned* p) {
    unsigned v;
    asm volatile("ld.global.acquire.gpu.b32 %0, [%1];" : "=r"(v) : "l"(p));
    return v;
}
__device__ __forceinline__ void st_rel(unsigned* p, unsigned v) {
    asm volatile("st.global.release.gpu.b32 [%0], %1;" :: "l"(p), "r"(v));
}

#define LD4(dst, base, srcp, ldfn) do {                       \
    float4 _t;                                                \
    _t = ldfn((srcp) + 0); dst[base+0]=_t.x; dst[base+1]=_t.y; dst[base+2]=_t.z; dst[base+3]=_t.w; \
} while (0)

__global__ void __launch_bounds__(32, 1)
dtw_ms_kernel(const float* __restrict__ x,
              const float* __restrict__ ker,
              float* __restrict__ out,
              int N)
{
    const int w    = blockIdx.x;
    const int lane = threadIdx.x;
    const int col  = (w << 5) + lane;
    const int NB   = N / RR;                 // 4096
    const int STEPS = NB + 31;
    const float INFV = __int_as_float(0x7f800000);
    const float kj = __ldg(&ker[col]);

    float ac[RR];
#pragma unroll
    for (int r = 0; r < RR; ++r) ac[r] = INFV;
    float uc     = (col == 0) ? 0.0f : INFV;  // up-carry   (v[-1] of next block)
    float dcarry = INFV;                      // diag-carry (left column, last row of prev block)

    // ---- boundary double buffer (only meaningful on lane0 of w>0) ----
    const bool cons = (w > 0) && (lane == 0);
    float bA[RR], bB[RR];
#pragma unroll
    for (int r = 0; r < RR; ++r) { bA[r] = INFV; bB[r] = INFV; }
    unsigned ready = 0;
    if (cons) {
        while ((ready = ld_acq(&g_flag[w - 1])) < 2u) __nanosleep(64);
        const float4* p = reinterpret_cast<const float4*>(&g_bnd[w - 1][0][0]);
        float4 t;
        t = __ldcg(p + 0); bA[0]=t.x;  bA[1]=t.y;  bA[2]=t.z;  bA[3]=t.w;
        t = __ldcg(p + 1); bA[4]=t.x;  bA[5]=t.y;  bA[6]=t.z;  bA[7]=t.w;
        t = __ldcg(p + 2); bA[8]=t.x;  bA[9]=t.y;  bA[10]=t.z; bA[11]=t.w;
        t = __ldcg(p + 3); bA[12]=t.x; bA[13]=t.y; bA[14]=t.z; bA[15]=t.w;
        t = __ldcg(p + 4); bB[0]=t.x;  bB[1]=t.y;  bB[2]=t.z;  bB[3]=t.w;
        t = __ldcg(p + 5); bB[4]=t.x;  bB[5]=t.y;  bB[6]=t.z;  bB[7]=t.w;
        t = __ldcg(p + 6); bB[8]=t.x;  bB[9]=t.y;  bB[10]=t.z; bB[11]=t.w;
        t = __ldcg(p + 7); bB[12]=t.x; bB[13]=t.y; bB[14]=t.z; bB[15]=t.w;
    }

    // ---- x prefetch buffer: holds the block used NEXT step (rotation at loop top) ----
    float xN[RR];
    {
        const float4* xp = reinterpret_cast<const float4*>(x);
        float4 t;
        t = __ldg(xp + 0); xN[0]=t.x;  xN[1]=t.y;  xN[2]=t.z;  xN[3]=t.w;
        t = __ldg(xp + 1); xN[4]=t.x;  xN[5]=t.y;  xN[6]=t.z;  xN[7]=t.w;
        t = __ldg(xp + 2); xN[8]=t.x;  xN[9]=t.y;  xN[10]=t.z; xN[11]=t.w;
        t = __ldg(xp + 3); xN[12]=t.x; xN[13]=t.y; xN[14]=t.z; xN[15]=t.w;
    }

    for (int s = 0; s < STEPS; ++s) {
        const int  b      = s - lane;
        const bool active = (b >= 0) && (b < NB);

        // 1) left-neighbor values (neighbor's ac from previous step)
        float left[RR];
#pragma unroll
        for (int r = 0; r < RR; ++r)
            left[r] = __shfl_up_sync(0xffffffffu, ac[r], 1);
        if (lane == 0) {
            if (w == 0) {
#pragma unroll
                for (int r = 0; r < RR; ++r) left[r] = INFV;
            } else {
#pragma unroll
                for (int r = 0; r < RR; ++r) left[r] = bA[r];
            }
        }

        // 2) rotate + distance-2 prefetch of the boundary (lane0 of w>0)
        if (cons) {
#pragma unroll
            for (int r = 0; r < RR; ++r) bA[r] = bB[r];
            const int nb2 = s + 2;
            if (nb2 < NB) {
                if (ready < (unsigned)(nb2 + 1)) {
                    while ((ready = ld_acq(&g_flag[w - 1])) < (unsigned)(nb2 + 1))
                        __nanosleep(32);
                }
                const float4* p = reinterpret_cast<const float4*>(&g_bnd[w - 1][nb2][0]);
                float4 t;
                t = __ldcg(p + 0); bB[0]=t.x;  bB[1]=t.y;  bB[2]=t.z;  bB[3]=t.w;
                t = __ldcg(p + 1); bB[4]=t.x;  bB[5]=t.y;  bB[6]=t.z;  bB[7]=t.w;
                t = __ldcg(p + 2); bB[8]=t.x;  bB[9]=t.y;  bB[10]=t.z; bB[11]=t.w;
                t = __ldcg(p + 3); bB[12]=t.x; bB[13]=t.y; bB[14]=t.z; bB[15]=t.w;
            }
        }

        // 3) rotate + prefetch x (next block for this lane)
        float xA[RR];
#pragma unroll
        for (int r = 0; r < RR; ++r) xA[r] = xN[r];
        {
            const int nb = b + 1;
            if (nb >= 0 && nb < NB) {
                const float4* xp = reinterpret_cast<const float4*>(x + nb * RR);
                float4 t;
                t = __ldg(xp + 0); xN[0]=t.x;  xN[1]=t.y;  xN[2]=t.z;  xN[3]=t.w;
                t = __ldg(xp + 1); xN[4]=t.x;  xN[5]=t.y;  xN[6]=t.z;  xN[7]=t.w;
                t = __ldg(xp + 2); xN[8]=t.x;  xN[9]=t.y;  xN[10]=t.z; xN[11]=t.w;
                t = __ldg(xp + 3); xN[12]=t.x; xN[13]=t.y; xN[14]=t.z; xN[15]=t.w;
            }
        }

        if (active) {
            // 4) squared distances + inclusive prefix sum S (off critical chain)
            float S[RR];
            {
                float d0 = kj - xA[0];
                S[0] = d0 * d0;
#pragma unroll
                for (int r = 1; r < RR; ++r) {
                    float d = kj - xA[r];
                    S[r] = fmaf(d, d, S[r - 1]);
                }
            }

            // 5) min-plus scan: chain is one FMNMX per cell
            float m    = uc;       // v[-1]
            float diag = dcarry;
#pragma unroll
            for (int r = 0; r < RR; ++r) {
                float e = fminf(diag, left[r]);
                float t = (r == 0) ? e : (e - S[r - 1]);
                m = fminf(m, t);
                ac[r] = m + S[r];
                diag = left[r];
            }
            uc     = ac[RR - 1];
            dcarry = left[RR - 1];

            // 6) publish boundary / emit outputs (lane31)
            if (lane == 31) {
                if (w == NCTA - 1) {
                    float4* o = reinterpret_cast<float4*>(out + b * RR);
                    o[0] = make_float4(ac[0],  ac[1],  ac[2],  ac[3]);
                    o[1] = make_float4(ac[4],  ac[5],  ac[6],  ac[7]);
                    o[2] = make_float4(ac[8],  ac[9],  ac[10], ac[11]);
                    o[3] = make_float4(ac[12], ac[13], ac[14], ac[15]);
                } else {
                    float4* p = reinterpret_cast<float4*>(&g_bnd[w][b][0]);
                    p[0] = make_float4(ac[0],  ac[1],  ac[2],  ac[3]);
                    p[1] = make_float4(ac[4],  ac[5],  ac[6],  ac[7]);
                    p[2] = make_float4(ac[8],  ac[9],  ac[10], ac[11]);
                    p[3] = make_float4(ac[12], ac[13], ac[14], ac[15]);
                    st_rel(&g_flag[w], (unsigned)(b + 1));
                }
            }
        }
    }
}

extern "C" void kernel_launch(void* const* d_in, const int* in_sizes, int n_in,
                              void* d_out, int out_size)
{
    const float* x;
    const float* ker;
    int N;
    if (n_in >= 2 && in_sizes[0] == KLEN && in_sizes[1] != KLEN) {
        ker = (const float*)d_in[0];
        x   = (const float*)d_in[1];
        N   = in_sizes[1];
    } else {
        x   = (const float*)d_in[0];
        ker = (const float*)d_in[1];
        N   = in_sizes[0];
    }
    float* out = (float*)d_out;

    dtw_ms_kernel<<<NCTA, 32>>>(x, ker, out, N);
}

// round 3
// speedup vs baseline: 1.9876x; 1.3775x over previous
#include <cuda_runtime.h>
#include <cstdint>

// DTW wavefront, warp-specialized, 16 CTAs (one per SM).
// CTA w owns columns [32w, 32w+32). Warp 0 = DP (lane j = column 32w+j,
// 16 rows per step, min-plus scan). Warp 1 = helper (precomputes per-block
// d^2 prefix sums S into smem ring, runs diagonally a few steps ahead).
// Warp 2 = import (neighbor CTA boundary: global -> smem ring).
// Warp 3 = export (own boundary col: smem -> global, + final outputs).

#define KLEN  512
#define RR    16
#define NCTA  16
#define NB    4096            // 65536 / 16
#define NSTEPS (NB + 31)

#define MIR_DS   640          // floats per mirror depth slot (32 lanes * 20)
#define MIR_LS   20           // floats per lane (16 + 4 pad -> conflict-free)
#define SR_LS    132          // floats per lane in S ring (8*16 + 4 pad)

__device__ float    g_bnd[NCTA][NB][16];
__device__ unsigned g_flag[NCTA];

__device__ __forceinline__ unsigned ld_acq_g(const unsigned* p) {
    unsigned v;
    asm volatile("ld.global.acquire.gpu.b32 %0, [%1];" : "=r"(v) : "l"(p));
    return v;
}
__device__ __forceinline__ void st_rel_g(unsigned* p, unsigned v) {
    asm volatile("st.global.release.gpu.b32 [%0], %1;" :: "l"(p), "r"(v));
}
__device__ __forceinline__ unsigned sld_acq(const unsigned* p) {
    unsigned a = (unsigned)__cvta_generic_to_shared((void*)p);
    unsigned v;
    asm volatile("ld.acquire.cta.shared.b32 %0, [%1];" : "=r"(v) : "r"(a));
    return v;
}
__device__ __forceinline__ void sst_rel(unsigned* p, unsigned v) {
    unsigned a = (unsigned)__cvta_generic_to_shared((void*)p);
    asm volatile("st.release.cta.shared.b32 [%0], %1;" :: "r"(a), "r"(v));
}

__global__ void __launch_bounds__(128, 1)
dtw_ws_kernel(const float* __restrict__ x,
              const float* __restrict__ ker,
              float* __restrict__ out)
{
    __shared__ __align__(16) float sm_mir[8 * MIR_DS];   // 20 KB  ac mirror ring
    __shared__ __align__(16) float sm_S[32 * SR_LS];     // 16.9 KB  S ring
    __shared__ __align__(16) float sm_bnd[16 * 16];      // 1 KB  neighbor boundary ring
    __shared__ unsigned sm_hctr;      // helper steps completed
    __shared__ unsigned sm_bctr;      // boundary blocks imported
    __shared__ unsigned sm_ectr;      // boundary blocks exported
    __shared__ unsigned sm_dpc[32];   // DP steps completed (per lane; readers use [31])

    const int w    = blockIdx.x;
    const int tid  = threadIdx.x;
    const int wid  = tid >> 5;
    const int lane = tid & 31;
    const float INFV = __int_as_float(0x7f800000);

    // ---- init ----
    if (tid == 0) { sm_hctr = 0; sm_bctr = 0; sm_ectr = 0; }
    if (wid == 0) sm_dpc[lane] = 0;
    for (int i = tid; i < 16 * 16; i += 128) sm_bnd[i] = INFV;   // CTA0 never overwrites
    __syncthreads();

    if (wid == 0) {
        // ================= DP warp =================
        const int col = (w << 5) + lane;
        float uc     = (col == 0) ? 0.0f : INFV;
        float dcarry = INFV;
        unsigned lim = 0;

        #define DP_WAIT3(COND_EXPR)                                            \
            if ((unsigned)s >= lim) {                                          \
                do { lim = (COND_EXPR); } while ((unsigned)s >= lim);          \
            }

        #define DP_BODY()                                                      \
        {                                                                      \
            const int b = s - lane;                                            \
            const float* lp = (lane == 0)                                      \
                ? &sm_bnd[(s & 15) * 16]                                       \
                : &sm_mir[((s - 1) & 7) * MIR_DS + (lane - 1) * MIR_LS];       \
            float4 L0 = *(const float4*)(lp + 0);                              \
            float4 L1 = *(const float4*)(lp + 4);                              \
            float4 L2 = *(const float4*)(lp + 8);                              \
            float4 L3 = *(const float4*)(lp + 12);                             \
            const float* sp = &sm_S[lane * SR_LS + (b & 7) * 16];              \
            float4 P0 = *(const float4*)(sp + 0);                              \
            float4 P1 = *(const float4*)(sp + 4);                              \
            float4 P2 = *(const float4*)(sp + 8);                              \
            float4 P3 = *(const float4*)(sp + 12);                             \
            float left[16] = {L0.x,L0.y,L0.z,L0.w, L1.x,L1.y,L1.z,L1.w,        \
                              L2.x,L2.y,L2.z,L2.w, L3.x,L3.y,L3.z,L3.w};       \
            float S[16]    = {P0.x,P0.y,P0.z,P0.w, P1.x,P1.y,P1.z,P1.w,        \
                              P2.x,P2.y,P2.z,P2.w, P3.x,P3.y,P3.z,P3.w};       \
            float ac[16];                                                      \
            float m = uc, prev = dcarry;                                       \
            _Pragma("unroll")                                                  \
            for (int r = 0; r < 16; ++r) {                                     \
                float e = fminf(prev, left[r]);                                \
                float t = (r == 0) ? e : (e - S[r - 1]);                       \
                m = fminf(m, t);                                               \
                ac[r] = m + S[r];                                              \
                prev = left[r];                                                \
            }                                                                  \
            uc = ac[15]; dcarry = left[15];                                    \
            float* mp = &sm_mir[(s & 7) * MIR_DS + lane * MIR_LS];             \
            *(float4*)(mp + 0)  = make_float4(ac[0],  ac[1],  ac[2],  ac[3]);  \
            *(float4*)(mp + 4)  = make_float4(ac[4],  ac[5],  ac[6],  ac[7]);  \
            *(float4*)(mp + 8)  = make_float4(ac[8],  ac[9],  ac[10], ac[11]); \
            *(float4*)(mp + 12) = make_float4(ac[12], ac[13], ac[14], ac[15]); \
        }

        // ---- fill: s in [0, 31) ----
        for (int s = 0; s < 31; ++s) {
            __syncwarp();
            DP_WAIT3(min(sld_acq(&sm_hctr), sld_acq(&sm_bctr)));
            if (lane <= s) DP_BODY();
            sst_rel(&sm_dpc[lane], (unsigned)(s + 1));
        }
        // ---- steady: s in [31, NB) ----
        for (int s = 31; s < NB; ++s) {
            __syncwarp();
            DP_WAIT3(min(min(sld_acq(&sm_hctr), sld_acq(&sm_bctr)),
                         sld_acq(&sm_ectr) + 37u));
            DP_BODY();
            sst_rel(&sm_dpc[lane], (unsigned)(s + 1));
        }
        // ---- drain: s in [NB, NB+31) ----
        for (int s = NB; s < NSTEPS; ++s) {
            __syncwarp();
            DP_WAIT3(min(sld_acq(&sm_hctr), sld_acq(&sm_ectr) + 37u));
            if (lane >= s - (NB - 1)) DP_BODY();
            sst_rel(&sm_dpc[lane], (unsigned)(s + 1));
        }
        #undef DP_BODY
        #undef DP_WAIT3
    }
    else if (wid == 1) {
        // ================= helper warp: S precompute =================
        const int col = (w << 5) + lane;
        const float kj = __ldg(&ker[col]);
        unsigned dpc = 0;
        for (int t = 0; t < NSTEPS; ++t) {
            // stay at most 6 steps ahead of the DP warp
            if ((unsigned)t > dpc + 6u) {
                do { dpc = sld_acq(&sm_dpc[31]); } while ((unsigned)t > dpc + 6u);
            }
            const int h = t - lane;
            if (h >= 0 && h < NB) {
                const float4* xp = (const float4*)(x + h * RR);
                float4 a = __ldg(xp + 0), b4 = __ldg(xp + 1);
                float4 c = __ldg(xp + 2), d4 = __ldg(xp + 3);
                float xv[16] = {a.x,a.y,a.z,a.w, b4.x,b4.y,b4.z,b4.w,
                                c.x,c.y,c.z,c.w, d4.x,d4.y,d4.z,d4.w};
                float S[16];
                float d0 = kj - xv[0];
                S[0] = d0 * d0;
                #pragma unroll
                for (int r = 1; r < 16; ++r) {
                    float d = kj - xv[r];
                    S[r] = fmaf(d, d, S[r - 1]);
                }
                float* sp = &sm_S[lane * SR_LS + (h & 7) * 16];
                *(float4*)(sp + 0)  = make_float4(S[0],  S[1],  S[2],  S[3]);
                *(float4*)(sp + 4)  = make_float4(S[4],  S[5],  S[6],  S[7]);
                *(float4*)(sp + 8)  = make_float4(S[8],  S[9],  S[10], S[11]);
                *(float4*)(sp + 12) = make_float4(S[12], S[13], S[14], S[15]);
            }
            __syncwarp();
            if (lane == 0) sst_rel(&sm_hctr, (unsigned)(t + 1));
        }
    }
    else if (wid == 2) {
        // ================= import warp (lane 0 only) =================
        if (w == 0) {
            if (lane == 0) sst_rel(&sm_bctr, (unsigned)NB);  // boundary = +inf, preset
        } else if (lane == 0) {
            unsigned dpc = 0, gf = 0;
            for (int n = 0; n < NB; ++n) {
                // backpressure: don't run >14 steps ahead of DP (ring depth 16)
                while ((unsigned)n > dpc + 14u) { dpc = sld_acq(&sm_dpc[31]); }
                while (gf < (unsigned)(n + 1)) {
                    gf = ld_acq_g(&g_flag[w - 1]);
                    if (gf < (unsigned)(n + 1)) __nanosleep(32);
                }
                const float4* gp = (const float4*)&g_bnd[w - 1][n][0];
                float4 v0 = __ldcg(gp + 0), v1 = __ldcg(gp + 1);
                float4 v2 = __ldcg(gp + 2), v3 = __ldcg(gp + 3);
                float* bp = &sm_bnd[(n & 15) * 16];
                *(float4*)(bp + 0)  = v0; *(float4*)(bp + 4)  = v1;
                *(float4*)(bp + 8)  = v2; *(float4*)(bp + 12) = v3;
                sst_rel(&sm_bctr, (unsigned)(n + 1));
            }
        }
    }
    else {
        // ================= export warp (lane 0 only) =================
        if (lane == 0) {
            unsigned dpc = 0;
            for (int b = 0; b < NB; ++b) {
                const unsigned need = (unsigned)(b + 32);   // lane31 computed block b at step b+31
                while (dpc < need) { dpc = sld_acq(&sm_dpc[31]); }
                const float* mp = &sm_mir[((b + 31) & 7) * MIR_DS + 31 * MIR_LS];
                float4 v0 = *(const float4*)(mp + 0);
                float4 v1 = *(const float4*)(mp + 4);
                float4 v2 = *(const float4*)(mp + 8);
                float4 v3 = *(const float4*)(mp + 12);
                if (w == NCTA - 1) {
                    float4* op = (float4*)(out + b * RR);
                    op[0] = v0; op[1] = v1; op[2] = v2; op[3] = v3;
                } else {
                    float4* gp = (float4*)&g_bnd[w][b][0];
                    __stcg(gp + 0, v0); __stcg(gp + 1, v1);
                    __stcg(gp + 2, v2); __stcg(gp + 3, v3);
                    st_rel_g(&g_flag[w], (unsigned)(b + 1));
                }
                sst_rel(&sm_ectr, (unsigned)(b + 1));
            }
        }
    }
}

extern "C" void kernel_launch(void* const* d_in, const int* in_sizes, int n_in,
                              void* d_out, int out_size)
{
    const float* x;
    const float* ker;
    if (n_in >= 2 && in_sizes[0] == KLEN && in_sizes[1] != KLEN) {
        ker = (const float*)d_in[0];
        x   = (const float*)d_in[1];
    } else {
        x   = (const float*)d_in[0];
        ker = (const float*)d_in[1];
    }
    float* out = (float*)d_out;

    dtw_ws_kernel<<<NCTA, 128>>>(x, ker, out);
}

// round 4
// speedup vs baseline: 2.9922x; 1.5054x over previous
#include <cuda_runtime.h>
#include <cstdint>

// DTW wavefront, warp-specialized, 16 CTAs (one per SM), batched boundary handoff.
// CTA w owns columns [32w, 32w+32). Warp 0 = DP. Warp 1 = helper (d^2 prefix sums,
// x double-buffered prefetch). Warp 2 = import (neighbor boundary, 8-block batches,
// warp-wide). Warp 3 = export (own boundary col / final output, 8-block batches).

#define KLEN   512
#define RR     16
#define NCTA   16
#define NB     4096            // 65536 / 16
#define NSTEPS (NB + 31)       // 4127
#define GB     8               // blocks per boundary batch
#define NBATCH (NB / GB)       // 512

#define MIR_DS 640             // floats per mirror slot (32 lanes * 20)
#define MIR_LS 20              // floats per lane (16 + 4 pad)
#define SR_LS  132             // floats per lane in S ring (8*16 + 4 pad)

__device__ float    g_bnd[NCTA][NB][16];
__device__ unsigned g_flag[NCTA];

__device__ __forceinline__ unsigned ld_acq_g(const unsigned* p) {
    unsigned v;
    asm volatile("ld.global.acquire.gpu.b32 %0, [%1];" : "=r"(v) : "l"(p));
    return v;
}
__device__ __forceinline__ void st_rel_g(unsigned* p, unsigned v) {
    asm volatile("st.global.release.gpu.b32 [%0], %1;" :: "l"(p), "r"(v));
}
__device__ __forceinline__ unsigned sld_acq(const unsigned* p) {
    unsigned a = (unsigned)__cvta_generic_to_shared((void*)p);
    unsigned v;
    asm volatile("ld.acquire.cta.shared.b32 %0, [%1];" : "=r"(v) : "r"(a));
    return v;
}
__device__ __forceinline__ void sst_rel(unsigned* p, unsigned v) {
    unsigned a = (unsigned)__cvta_generic_to_shared((void*)p);
    asm volatile("st.release.cta.shared.b32 [%0], %1;" :: "r"(a), "r"(v));
}

__global__ void __launch_bounds__(128, 1)
dtw_ws2_kernel(const float* __restrict__ x,
               const float* __restrict__ ker,
               float* __restrict__ out)
{
    __shared__ __align__(16) float sm_mir[8 * MIR_DS];   // 20 KB  ac mirror ring
    __shared__ __align__(16) float sm_S[32 * SR_LS];     // 16.5 KB S ring
    __shared__ __align__(16) float sm_bnd[16 * 16];      // 1 KB   neighbor boundary ring
    __shared__ __align__(16) float sm_exp[16 * 16];      // 1 KB   export (lane31) ring
    __shared__ unsigned sm_hctr;   // helper diagonals completed
    __shared__ unsigned sm_bctr;   // boundary blocks imported
    __shared__ unsigned sm_ectr;   // boundary blocks exported
    __shared__ unsigned sm_dpc;    // DP steps fully completed (published by lane31)

    const int w    = blockIdx.x;
    const int tid  = threadIdx.x;
    const int wid  = tid >> 5;
    const int lane = tid & 31;
    const float INFV = __int_as_float(0x7f800000);

    if (tid == 0) {
        sm_hctr = 0; sm_ectr = 0; sm_dpc = 0;
        sm_bctr = (w == 0) ? 0x7fffffffu : 0u;   // CTA0 boundary is constant +inf
    }
    for (int i = tid; i < 16 * 16; i += 128) sm_bnd[i] = INFV;
    __syncthreads();

    if (wid == 0) {
        // ========================= DP warp =========================
        float uc     = (w == 0 && lane == 0) ? 0.0f : INFV;
        float dcarry = INFV;
        unsigned lim = 0;

        for (int s = 0; s < NSTEPS; ++s) {
            __syncwarp();
            if (lane == 31) sst_rel(&sm_dpc, (unsigned)s);   // steps 0..s-1 complete

            if ((unsigned)s >= lim) {
                unsigned h, bc, e;
                do {
                    h  = sld_acq(&sm_hctr);
                    bc = sld_acq(&sm_bctr);
                    e  = sld_acq(&sm_ectr) + 44u;
                    lim = min(h, min(bc, e));
                } while ((unsigned)s >= lim);
            }

            const int b = s - lane;
            if ((unsigned)b < (unsigned)NB) {
                const float* lp = (lane == 0)
                    ? &sm_bnd[(s & 15) * 16]
                    : &sm_mir[((s - 1) & 7) * MIR_DS + (lane - 1) * MIR_LS];
                float4 L0 = *(const float4*)(lp + 0);
                float4 L1 = *(const float4*)(lp + 4);
                float4 L2 = *(const float4*)(lp + 8);
                float4 L3 = *(const float4*)(lp + 12);
                const float* sp = &sm_S[lane * SR_LS + (b & 7) * 16];
                float4 P0 = *(const float4*)(sp + 0);
                float4 P1 = *(const float4*)(sp + 4);
                float4 P2 = *(const float4*)(sp + 8);
                float4 P3 = *(const float4*)(sp + 12);
                float left[16] = {L0.x,L0.y,L0.z,L0.w, L1.x,L1.y,L1.z,L1.w,
                                  L2.x,L2.y,L2.z,L2.w, L3.x,L3.y,L3.z,L3.w};
                float S[16]    = {P0.x,P0.y,P0.z,P0.w, P1.x,P1.y,P1.z,P1.w,
                                  P2.x,P2.y,P2.z,P2.w, P3.x,P3.y,P3.z,P3.w};
                float ac[16];
                float m = uc, prev = dcarry;
                #pragma unroll
                for (int r = 0; r < 16; ++r) {
                    float e = fminf(prev, left[r]);
                    float t = (r == 0) ? e : (e - S[r - 1]);
                    m = fminf(m, t);
                    ac[r] = m + S[r];
                    prev = left[r];
                }
                uc = ac[15]; dcarry = left[15];

                float* mp = &sm_mir[(s & 7) * MIR_DS + lane * MIR_LS];
                *(float4*)(mp + 0)  = make_float4(ac[0],  ac[1],  ac[2],  ac[3]);
                *(float4*)(mp + 4)  = make_float4(ac[4],  ac[5],  ac[6],  ac[7]);
                *(float4*)(mp + 8)  = make_float4(ac[8],  ac[9],  ac[10], ac[11]);
                *(float4*)(mp + 12) = make_float4(ac[12], ac[13], ac[14], ac[15]);
                if (lane == 31) {
                    float* ep = &sm_exp[(b & 15) * 16];
                    *(float4*)(ep + 0)  = make_float4(ac[0],  ac[1],  ac[2],  ac[3]);
                    *(float4*)(ep + 4)  = make_float4(ac[4],  ac[5],  ac[6],  ac[7]);
                    *(float4*)(ep + 8)  = make_float4(ac[8],  ac[9],  ac[10], ac[11]);
                    *(float4*)(ep + 12) = make_float4(ac[12], ac[13], ac[14], ac[15]);
                }
            }
        }
        __syncwarp();
        if (lane == 31) sst_rel(&sm_dpc, (unsigned)NSTEPS);
    }
    else if (wid == 1) {
        // ========================= helper warp =========================
        // S[b][r] = inclusive prefix sum of (ker[col]-x[b*16+r])^2, distance-2
        // x prefetch via parity-split double buffer.
        const float kj = __ldg(&ker[(w << 5) + lane]);
        float xE[16], xO[16];
        {   // preload: xE <- block (lane&1), xO <- block ((lane&1)^1)
            const float4* pe = (const float4*)(x + (lane & 1) * RR);
            const float4* po = (const float4*)(x + ((lane & 1) ^ 1) * RR);
            float4 t;
            t = __ldg(pe+0); xE[0]=t.x; xE[1]=t.y; xE[2]=t.z; xE[3]=t.w;
            t = __ldg(pe+1); xE[4]=t.x; xE[5]=t.y; xE[6]=t.z; xE[7]=t.w;
            t = __ldg(pe+2); xE[8]=t.x; xE[9]=t.y; xE[10]=t.z; xE[11]=t.w;
            t = __ldg(pe+3); xE[12]=t.x; xE[13]=t.y; xE[14]=t.z; xE[15]=t.w;
            t = __ldg(po+0); xO[0]=t.x; xO[1]=t.y; xO[2]=t.z; xO[3]=t.w;
            t = __ldg(po+1); xO[4]=t.x; xO[5]=t.y; xO[6]=t.z; xO[7]=t.w;
            t = __ldg(po+2); xO[8]=t.x; xO[9]=t.y; xO[10]=t.z; xO[11]=t.w;
            t = __ldg(po+3); xO[12]=t.x; xO[13]=t.y; xO[14]=t.z; xO[15]=t.w;
        }
        unsigned dpc = 0;

        #define HSTEP(T, XB)                                                   \
        {                                                                      \
            const int t_ = (T);                                                \
            __syncwarp();                                                      \
            if (lane == 0) sst_rel(&sm_hctr, (unsigned)t_);                    \
            if ((unsigned)t_ > dpc + 7u) {                                     \
                do { dpc = sld_acq(&sm_dpc); } while ((unsigned)t_ > dpc + 7u);\
            }                                                                  \
            const int h = t_ - lane;                                           \
            if ((unsigned)h < (unsigned)NB) {                                  \
                float S[16];                                                   \
                float d0 = kj - XB[0];                                         \
                S[0] = d0 * d0;                                                \
                _Pragma("unroll")                                              \
                for (int r = 1; r < 16; ++r) {                                 \
                    float d = kj - XB[r];                                      \
                    S[r] = fmaf(d, d, S[r - 1]);                               \
                }                                                              \
                float* sp = &sm_S[lane * SR_LS + (h & 7) * 16];                \
                *(float4*)(sp + 0)  = make_float4(S[0],  S[1],  S[2],  S[3]);  \
                *(float4*)(sp + 4)  = make_float4(S[4],  S[5],  S[6],  S[7]);  \
                *(float4*)(sp + 8)  = make_float4(S[8],  S[9],  S[10], S[11]); \
                *(float4*)(sp + 12) = make_float4(S[12], S[13], S[14], S[15]); \
            }                                                                  \
            const int hn = h + 2;                                              \
            if ((unsigned)hn < (unsigned)NB) {                                 \
                const float4* xp = (const float4*)(x + hn * RR);               \
                float4 a = __ldg(xp+0), b4 = __ldg(xp+1);                      \
                float4 c = __ldg(xp+2), d4 = __ldg(xp+3);                      \
                XB[0]=a.x;  XB[1]=a.y;  XB[2]=a.z;  XB[3]=a.w;                 \
                XB[4]=b4.x; XB[5]=b4.y; XB[6]=b4.z; XB[7]=b4.w;                \
                XB[8]=c.x;  XB[9]=c.y;  XB[10]=c.z; XB[11]=c.w;                \
                XB[12]=d4.x;XB[13]=d4.y;XB[14]=d4.z;XB[15]=d4.w;               \
            }                                                                  \
        }

        for (int t = 0; t < NSTEPS + 1; t += 2) {
            HSTEP(t,     xE);
            HSTEP(t + 1, xO);
        }
        #undef HSTEP
        __syncwarp();
        if (lane == 0) sst_rel(&sm_hctr, 0x7fffffffu);
    }
    else if (wid == 2) {
        // ========================= import warp =========================
        if (w > 0) {
            unsigned dpc = 0, gf = 0;
            for (int k = 0; k < NBATCH; ++k) {
                const int n0 = k * GB;
                const unsigned top = (unsigned)(n0 + GB - 1);
                if (top > dpc + 15u) {      // ring overwrite backpressure
                    do { dpc = sld_acq(&sm_dpc); } while (top > dpc + 15u);
                }
                if (lane == 0) {
                    while (gf < (unsigned)(n0 + GB)) {
                        gf = ld_acq_g(&g_flag[w - 1]);
                        if (gf < (unsigned)(n0 + GB)) __nanosleep(64);
                    }
                }
                __syncwarp();
                const float4* gp = (const float4*)&g_bnd[w - 1][n0][0];
                float4 v = __ldcg(gp + lane);            // 128 floats, whole batch
                float4* bp = (float4*)&sm_bnd[(n0 & 15) * 16];
                bp[lane] = v;
                __syncwarp();
                if (lane == 0) sst_rel(&sm_bctr, (unsigned)(n0 + GB));
            }
            if (lane == 0) sst_rel(&sm_bctr, 0x7fffffffu);
        }
    }
    else {
        // ========================= export warp =========================
        unsigned dpc = 0;
        for (int k = 0; k < NBATCH; ++k) {
            const int b0 = k * GB;
            const unsigned need = (unsigned)(b0 + GB + 31);   // dpc >= 8k+39
            if (dpc < need) {
                do { dpc = sld_acq(&sm_dpc); } while (dpc < need);
            }
            const float4* ep = (const float4*)&sm_exp[(b0 & 15) * 16];
            float4 v = ep[lane];
            if (w == NCTA - 1) {
                float4* op = (float4*)(out + b0 * 16);
                op[lane] = v;
            } else {
                float4* gp = (float4*)&g_bnd[w][b0][0];
                __stcg(gp + lane, v);
            }
            __syncwarp();
            if (lane == 0) {
                if (w < NCTA - 1) st_rel_g(&g_flag[w], (unsigned)(b0 + GB));
                sst_rel(&sm_ectr, (unsigned)(b0 + GB));
            }
        }
    }
}

extern "C" void kernel_launch(void* const* d_in, const int* in_sizes, int n_in,
                              void* d_out, int out_size)
{
    const float* x;
    const float* ker;
    if (n_in >= 2 && in_sizes[0] == KLEN && in_sizes[1] != KLEN) {
        ker = (const float*)d_in[0];
        x   = (const float*)d_in[1];
    } else {
        x   = (const float*)d_in[0];
        ker = (const float*)d_in[1];
    }
    float* out = (float*)d_out;

    dtw_ws2_kernel<<<NCTA, 128>>>(x, ker, out);
}

// round 5
// speedup vs baseline: 4.3439x; 1.4517x over previous
#include <cuda_runtime.h>
#include <cstdint>

// DTW wavefront, warp-specialized, 16 CTAs (one per SM), 8-step supersteps,
// barrier-free DP loop (convergent warp, predicated body).
// Warp 0 = DP (lane j = column 32w+j, 16 rows/step, min-plus scan).
// Warp 1 = helper (d^2 prefix sums into per-lane S ring, depth 16).
// Warp 2 = import (neighbor boundary, 8-block batches). Warp 3 = export.

#define KLEN   512
#define RR     16
#define NCTA   16
#define NB     4096            // 65536 / 16
#define NSP    4128            // padded step count (mult of 8), real = 4127
#define GB     8               // blocks per boundary batch
#define NBATCH (NB / GB)       // 512

#define MIR_DS 640             // floats per mirror slot (32 lanes * 20)
#define MIR_LS 20              // 16 + 4 pad (conflict-free for .128)
#define SR_LS  260             // 16 slots * 16 + 4 pad per lane

__device__ float    g_bnd[NCTA][NB][16];
__device__ unsigned g_flag[NCTA];

__device__ __forceinline__ unsigned ld_acq_g(const unsigned* p) {
    unsigned v;
    asm volatile("ld.global.acquire.gpu.b32 %0, [%1];" : "=r"(v) : "l"(p));
    return v;
}
__device__ __forceinline__ void st_rel_g(unsigned* p, unsigned v) {
    asm volatile("st.global.release.gpu.b32 [%0], %1;" :: "l"(p), "r"(v));
}
__device__ __forceinline__ unsigned sld_acq(const unsigned* p) {
    unsigned a = (unsigned)__cvta_generic_to_shared((void*)p);
    unsigned v;
    asm volatile("ld.acquire.cta.shared.b32 %0, [%1];" : "=r"(v) : "r"(a));
    return v;
}
__device__ __forceinline__ void sst_rel(unsigned* p, unsigned v) {
    unsigned a = (unsigned)__cvta_generic_to_shared((void*)p);
    asm volatile("st.release.cta.shared.b32 [%0], %1;" :: "r"(a), "r"(v));
}

__global__ void __launch_bounds__(128, 1)
dtw_ws3_kernel(const float* __restrict__ x,
               const float* __restrict__ ker,
               float* __restrict__ out)
{
    __shared__ __align__(16) float sm_mir[8 * MIR_DS];   // 20 KB   ac mirror ring
    __shared__ __align__(16) float sm_S[32 * SR_LS];     // 33.3 KB S ring (per-lane, depth 16)
    __shared__ __align__(16) float sm_bnd[32 * 16];      // 2 KB    neighbor boundary ring
    __shared__ __align__(16) float sm_exp[16 * 16];      // 1 KB    export ring
    __shared__ unsigned sm_hctr, sm_bctr, sm_ectr, sm_dpc;

    const int w    = blockIdx.x;
    const int tid  = threadIdx.x;
    const int wid  = tid >> 5;
    const int lane = tid & 31;
    const float INFV = __int_as_float(0x7f800000);

    if (tid == 0) {
        sm_hctr = 0; sm_ectr = 0; sm_dpc = 0;
        sm_bctr = (w == 0) ? 0x7ffffff0u : 0u;   // CTA0 boundary is constant +inf
    }
    for (int i = tid; i < 32 * 16; i += 128) sm_bnd[i] = INFV;
    __syncthreads();

    if (wid == 0) {
        // ========================= DP warp =========================
        const bool col0 = (w == 0) && (lane == 0);
        float uc = col0 ? 0.0f : INFV;
        float dc = INFV;
        int hc = 0, bc = 0, ec = 0;
        if (w == 0) bc = 0x7ffffff0;

        for (int s0 = 0; s0 < NSP; s0 += 8) {
            if (lane == 31) sst_rel(&sm_dpc, (unsigned)s0);   // steps <= s0-1 done
            if (hc < s0 + 8) { do { hc = (int)sld_acq(&sm_hctr); } while (hc < s0 + 8); }
            if (bc < s0 + 8) { do { bc = (int)sld_acq(&sm_bctr); } while (bc < s0 + 8); }
            if (ec < s0 - 32) { do { ec = (int)sld_acq(&sm_ectr); } while (ec < s0 - 32); }

            #pragma unroll
            for (int k = 0; k < 8; ++k) {
                const int s = s0 + k;
                const int b = s - lane;

                // left source: lane0 -> bnd ring slot (s&31); else mirror slot ((s-1)&7), lane-1
                const float* lpm = &sm_mir[((s + 7) & 7) * MIR_DS + (lane - 1) * MIR_LS];
                const float* lpb = &sm_bnd[(s & 31) << 4];
                const float* lp  = (lane == 0) ? lpb : lpm;
                float4 L0 = *(const float4*)(lp + 0);
                float4 L1 = *(const float4*)(lp + 4);
                float4 L2 = *(const float4*)(lp + 8);
                float4 L3 = *(const float4*)(lp + 12);

                const float* sp = &sm_S[lane * SR_LS + ((b & 15) << 4)];
                float4 P0 = *(const float4*)(sp + 0);
                float4 P1 = *(const float4*)(sp + 4);
                float4 P2 = *(const float4*)(sp + 8);
                float4 P3 = *(const float4*)(sp + 12);

                // carry reset at first real block (branch-free / predicated)
                if (b == 0) { uc = col0 ? 0.0f : INFV; dc = INFV; }

                float left[16] = {L0.x,L0.y,L0.z,L0.w, L1.x,L1.y,L1.z,L1.w,
                                  L2.x,L2.y,L2.z,L2.w, L3.x,L3.y,L3.z,L3.w};
                float S[16]    = {P0.x,P0.y,P0.z,P0.w, P1.x,P1.y,P1.z,P1.w,
                                  P2.x,P2.y,P2.z,P2.w, P3.x,P3.y,P3.z,P3.w};
                float ac[16];
                float m = uc, prev = dc;
                #pragma unroll
                for (int r = 0; r < 16; ++r) {
                    float e = fminf(prev, left[r]);
                    float t = (r == 0) ? e : (e - S[r - 1]);
                    m = fminf(m, t);
                    ac[r] = m + S[r];
                    prev = left[r];
                }
                uc = ac[15];
                dc = left[15];

                float* mp = &sm_mir[(s & 7) * MIR_DS + lane * MIR_LS];
                *(float4*)(mp + 0)  = make_float4(ac[0],  ac[1],  ac[2],  ac[3]);
                *(float4*)(mp + 4)  = make_float4(ac[4],  ac[5],  ac[6],  ac[7]);
                *(float4*)(mp + 8)  = make_float4(ac[8],  ac[9],  ac[10], ac[11]);
                *(float4*)(mp + 12) = make_float4(ac[12], ac[13], ac[14], ac[15]);
                if (lane == 31) {
                    float* ep = &sm_exp[(b & 15) << 4];
                    *(float4*)(ep + 0)  = make_float4(ac[0],  ac[1],  ac[2],  ac[3]);
                    *(float4*)(ep + 4)  = make_float4(ac[4],  ac[5],  ac[6],  ac[7]);
                    *(float4*)(ep + 8)  = make_float4(ac[8],  ac[9],  ac[10], ac[11]);
                    *(float4*)(ep + 12) = make_float4(ac[12], ac[13], ac[14], ac[15]);
                }
            }
        }
        if (lane == 31) sst_rel(&sm_dpc, (unsigned)(NSP + 64));
    }
    else if (wid == 1) {
        // ========================= helper warp =========================
        const float kj = __ldg(&ker[(w << 5) + lane]);
        int dpc = 0;
        for (int t0 = 0; t0 < NSP; t0 += 8) {
            if (lane == 0) sst_rel(&sm_hctr, (unsigned)t0);       // steps <= t0-1 done
            if (dpc < t0 - 8) { do { dpc = (int)sld_acq(&sm_dpc); } while (dpc < t0 - 8); }
            #pragma unroll
            for (int k = 0; k < 8; ++k) {
                const int t = t0 + k;
                const int h = t - lane;
                if ((unsigned)h < (unsigned)NB) {
                    const float4* xp = (const float4*)(x + h * RR);
                    float4 a = __ldg(xp + 0), b4 = __ldg(xp + 1);
                    float4 c = __ldg(xp + 2), d4 = __ldg(xp + 3);
                    float xv[16] = {a.x,a.y,a.z,a.w, b4.x,b4.y,b4.z,b4.w,
                                    c.x,c.y,c.z,c.w, d4.x,d4.y,d4.z,d4.w};
                    float S[16];
                    float d0 = kj - xv[0];
                    S[0] = d0 * d0;
                    #pragma unroll
                    for (int r = 1; r < 16; ++r) {
                        float d = kj - xv[r];
                        S[r] = fmaf(d, d, S[r - 1]);
                    }
                    float* sp = &sm_S[lane * SR_LS + ((h & 15) << 4)];
                    *(float4*)(sp + 0)  = make_float4(S[0],  S[1],  S[2],  S[3]);
                    *(float4*)(sp + 4)  = make_float4(S[4],  S[5],  S[6],  S[7]);
                    *(float4*)(sp + 8)  = make_float4(S[8],  S[9],  S[10], S[11]);
                    *(float4*)(sp + 12) = make_float4(S[12], S[13], S[14], S[15]);
                }
            }
        }
        if (lane == 0) sst_rel(&sm_hctr, (unsigned)(NSP + 64));
    }
    else if (wid == 2) {
        // ========================= import warp =========================
        if (w > 0) {
            int dpc = 0;
            unsigned gf = 0;
            for (int k = 0; k < NBATCH; ++k) {
                const int n0 = k * GB;
                if (dpc < n0 - 24) { do { dpc = (int)sld_acq(&sm_dpc); } while (dpc < n0 - 24); }
                const unsigned need = (unsigned)(n0 + GB);
                while (gf < need) {                       // all lanes poll (per-lane acquire)
                    gf = ld_acq_g(&g_flag[w - 1]);
                    if (gf < need) __nanosleep(64);
                }
                float4 v = __ldcg((const float4*)&g_bnd[w - 1][n0][0] + lane);
                *((float4*)&sm_bnd[(n0 & 31) << 4] + lane) = v;
                __syncwarp();
                if (lane == 0) sst_rel(&sm_bctr, (unsigned)(n0 + GB));
            }
            if (lane == 0) sst_rel(&sm_bctr, 0x7ffffff0u);
        }
    }
    else {
        // ========================= export warp =========================
        int dpc = 0;
        for (int k = 0; k < NBATCH; ++k) {
            const int b0 = k * GB;
            const int need = b0 + GB + 32;     // lane31 done step b0+38 -> dpc >= b0+40
            if (dpc < need) { do { dpc = (int)sld_acq(&sm_dpc); } while (dpc < need); }
            float4 v = *((const float4*)&sm_exp[(b0 & 15) << 4] + lane);
            if (w == NCTA - 1) {
                ((float4*)(out + (b0 << 4)))[lane] = v;
            } else {
                __stcg((float4*)&g_bnd[w][b0][0] + lane, v);
            }
            __syncwarp();
            if (lane == 0) {
                if (w < NCTA - 1) st_rel_g(&g_flag[w], (unsigned)(b0 + GB));
                sst_rel(&sm_ectr, (unsigned)(b0 + GB));
            }
        }
    }
}

extern "C" void kernel_launch(void* const* d_in, const int* in_sizes, int n_in,
                              void* d_out, int out_size)
{
    const float* x;
    const float* ker;
    if (n_in >= 2 && in_sizes[0] == KLEN && in_sizes[1] != KLEN) {
        ker = (const float*)d_in[0];
        x   = (const float*)d_in[1];
    } else {
        x   = (const float*)d_in[0];
        ker = (const float*)d_in[1];
    }
    float* out = (float*)d_out;

    dtw_ws3_kernel<<<NCTA, 128>>>(x, ker, out);
}

// round 11
// speedup vs baseline: 4.4684x; 1.0287x over previous
#include <cuda_runtime.h>
#include <cstdint>

// DTW wavefront, warp-specialized, 16 CTAs (one per SM), 8-step supersteps,
// deep rings (>=2 supersteps slack on every handshake), barrier-free DP loop.
// Warp 0 = DP (lane j = column 32w+j, 16 rows/step, min-plus scan).
// Warp 1 = helper (d^2 prefix sums, per-lane S ring depth 32).
// Warp 2 = import (neighbor boundary, 8-block batches, ring depth 32).
// Warp 3 = export (own boundary col / final output, exp ring depth 32).

#define KLEN   512
#define RR     16
#define NCTA   16
#define NB     4096            // 65536 / 16
#define NSP    4128            // padded step count (mult of 8), real = 4127
#define GB     8
#define NBATCH (NB / GB)       // 512

#define MIR_DS 640             // floats per mirror slot (32 lanes * 20)
#define MIR_LS 20              // 16 + 4 pad (conflict-free .128)
#define SR_LS  516             // 32 slots * 16 + 4 pad per lane (stride%32==4: conflict-free)

__device__ float    g_bnd[NCTA][NB][16];
__device__ unsigned g_flag[NCTA];

__device__ __forceinline__ unsigned ld_acq_g(const unsigned* p) {
    unsigned v;
    asm volatile("ld.global.acquire.gpu.b32 %0, [%1];" : "=r"(v) : "l"(p));
    return v;
}
__device__ __forceinline__ void st_rel_g(unsigned* p, unsigned v) {
    asm volatile("st.global.release.gpu.b32 [%0], %1;" :: "l"(p), "r"(v));
}
__device__ __forceinline__ unsigned sld_acq(const unsigned* p) {
    unsigned a = (unsigned)__cvta_generic_to_shared((void*)p);
    unsigned v;
    asm volatile("ld.acquire.cta.shared.b32 %0, [%1];" : "=r"(v) : "r"(a));
    return v;
}
__device__ __forceinline__ void sst_rel(unsigned* p, unsigned v) {
    unsigned a = (unsigned)__cvta_generic_to_shared((void*)p);
    asm volatile("st.release.cta.shared.b32 [%0], %1;" :: "r"(a), "r"(v));
}

__global__ void __launch_bounds__(128, 1)
dtw_ws4_kernel(const float* __restrict__ x,
               const float* __restrict__ ker,
               float* __restrict__ out)
{
    __shared__ __align__(16) float sm_mir[8 * MIR_DS];   // 20 KB
    __shared__ __align__(16) float sm_S[32 * SR_LS];     // 64.5 KB
    __shared__ __align__(16) float sm_bnd[32 * 16];      // 2 KB
    __shared__ __align__(16) float sm_exp[32 * 16];      // 2 KB
    __shared__ unsigned sm_hctr, sm_bctr, sm_ectr, sm_dpc;

    const int w    = blockIdx.x;
    const int tid  = threadIdx.x;
    const int wid  = tid >> 5;
    const int lane = tid & 31;
    const float INFV = __int_as_float(0x7f800000);

    if (tid == 0) {
        sm_hctr = 0; sm_ectr = 0; sm_dpc = 0;
        sm_bctr = (w == 0) ? 0x7ffffff0u : 0u;
    }
    for (int i = tid; i < 32 * 16; i += 128) sm_bnd[i] = INFV;
    __syncthreads();

    if (wid == 0) {
        // ========================= DP warp =========================
        const bool col0 = (w == 0) && (lane == 0);
        float uc = col0 ? 0.0f : INFV;
        float dc = INFV;
        int hc = 0, bc = (w == 0) ? 0x7ffffff0 : 0, ec = 0;

        // DP_STEP(k, RESET): one wavefront step inside a superstep.
        #define DP_STEP(kk, RESET)                                             \
        {                                                                      \
            const int k = (kk);                                                \
            const int s = s0 + k;                                              \
            const int b = s - lane;                                            \
            const float* lp = (lane == 0)                                      \
                ? &sm_bnd[(bOff + k) << 4]                                     \
                : &sm_mir[((k + 7) & 7) * MIR_DS + (lane - 1) * MIR_LS];       \
            float4 L0 = *(const float4*)(lp + 0);                              \
            float4 L1 = *(const float4*)(lp + 4);                              \
            float4 L2 = *(const float4*)(lp + 8);                              \
            float4 L3 = *(const float4*)(lp + 12);                             \
            const float* sp = &sm_S[lane * SR_LS + (((sB + k) & 31) << 4)];    \
            float4 P0 = *(const float4*)(sp + 0);                              \
            float4 P1 = *(const float4*)(sp + 4);                              \
            float4 P2 = *(const float4*)(sp + 8);                              \
            float4 P3 = *(const float4*)(sp + 12);                             \
            if (RESET && b == 0) { uc = col0 ? 0.0f : INFV; dc = INFV; }       \
            float left[16] = {L0.x,L0.y,L0.z,L0.w, L1.x,L1.y,L1.z,L1.w,        \
                              L2.x,L2.y,L2.z,L2.w, L3.x,L3.y,L3.z,L3.w};       \
            float S[16]    = {P0.x,P0.y,P0.z,P0.w, P1.x,P1.y,P1.z,P1.w,        \
                              P2.x,P2.y,P2.z,P2.w, P3.x,P3.y,P3.z,P3.w};       \
            float ac[16];                                                      \
            float m = uc, prev = dc;                                           \
            _Pragma("unroll")                                                  \
            for (int r = 0; r < 16; ++r) {                                     \
                float e = fminf(prev, left[r]);                                \
                float t = (r == 0) ? e : (e - S[r - 1]);                       \
                m = fminf(m, t);                                               \
                ac[r] = m + S[r];                                              \
                prev = left[r];                                                \
            }                                                                  \
            uc = ac[15]; dc = left[15];                                        \
            float* mp = &sm_mir[k * MIR_DS + lane * MIR_LS];                   \
            *(float4*)(mp + 0)  = make_float4(ac[0],  ac[1],  ac[2],  ac[3]);  \
            *(float4*)(mp + 4)  = make_float4(ac[4],  ac[5],  ac[6],  ac[7]);  \
            *(float4*)(mp + 8)  = make_float4(ac[8],  ac[9],  ac[10], ac[11]); \
            *(float4*)(mp + 12) = make_float4(ac[12], ac[13], ac[14], ac[15]); \
            if (lane == 31) {                                                  \
                float* ep = &sm_exp[((eB + k) & 31) << 4];                     \
                *(float4*)(ep + 0)  = make_float4(ac[0],  ac[1],  ac[2],  ac[3]);  \
                *(float4*)(ep + 4)  = make_float4(ac[4],  ac[5],  ac[6],  ac[7]);  \
                *(float4*)(ep + 8)  = make_float4(ac[8],  ac[9],  ac[10], ac[11]); \
                *(float4*)(ep + 12) = make_float4(ac[12], ac[13], ac[14], ac[15]); \
            }                                                                  \
        }

        #define DP_SUPER(RESET)                                                \
        {                                                                      \
            if (lane == 31) sst_rel(&sm_dpc, (unsigned)s0);                    \
            if (hc < s0 + 8) { do { hc = (int)sld_acq(&sm_hctr); } while (hc < s0 + 8); } \
            if (bc < s0 + 8) { do { bc = (int)sld_acq(&sm_bctr); } while (bc < s0 + 8); } \
            if (ec < s0 - 48) { do { ec = (int)sld_acq(&sm_ectr); } while (ec < s0 - 48); } \
            const int bOff = s0 & 31;                                          \
            const int eB   = (s0 & 31) + 1;                                    \
            const int sB   = (s0 - lane) & 31;                                 \
            DP_STEP(0, RESET) DP_STEP(1, RESET) DP_STEP(2, RESET)              \
            DP_STEP(3, RESET) DP_STEP(4, RESET) DP_STEP(5, RESET)              \
            DP_STEP(6, RESET) DP_STEP(7, RESET)                                \
        }

        // fill supersteps (carry resets possible: s < 32)
        for (int s0 = 0; s0 < 32; s0 += 8) DP_SUPER(true)
        // steady + drain (no resets)
        for (int s0 = 32; s0 < NSP; s0 += 8) DP_SUPER(false)

        #undef DP_SUPER
        #undef DP_STEP
        if (lane == 31) sst_rel(&sm_dpc, (unsigned)(NSP + 64));
    }
    else if (wid == 1) {
        // ========================= helper warp =========================
        const float kj = __ldg(&ker[(w << 5) + lane]);
        int dpc = 0;
        for (int t0 = 0; t0 < NSP; t0 += 8) {
            if (lane == 0) sst_rel(&sm_hctr, (unsigned)t0);
            if (dpc < t0 - 24) { do { dpc = (int)sld_acq(&sm_dpc); } while (dpc < t0 - 24); }
            #pragma unroll
            for (int k = 0; k < 8; ++k) {
                const int h = t0 + k - lane;
                if ((unsigned)h < (unsigned)NB) {
                    const float4* xp = (const float4*)(x + h * RR);
                    float4 a = __ldg(xp + 0), b4 = __ldg(xp + 1);
                    float4 c = __ldg(xp + 2), d4 = __ldg(xp + 3);
                    float xv[16] = {a.x,a.y,a.z,a.w, b4.x,b4.y,b4.z,b4.w,
                                    c.x,c.y,c.z,c.w, d4.x,d4.y,d4.z,d4.w};
                    float S[16];
                    float d0 = kj - xv[0];
                    S[0] = d0 * d0;
                    #pragma unroll
                    for (int r = 1; r < 16; ++r) {
                        float d = kj - xv[r];
                        S[r] = fmaf(d, d, S[r - 1]);
                    }
                    float* sp = &sm_S[lane * SR_LS + ((h & 31) << 4)];
                    *(float4*)(sp + 0)  = make_float4(S[0],  S[1],  S[2],  S[3]);
                    *(float4*)(sp + 4)  = make_float4(S[4],  S[5],  S[6],  S[7]);
                    *(float4*)(sp + 8)  = make_float4(S[8],  S[9],  S[10], S[11]);
                    *(float4*)(sp + 12) = make_float4(S[12], S[13], S[14], S[15]);
                }
            }
        }
        if (lane == 0) sst_rel(&sm_hctr, (unsigned)(NSP + 64));
    }
    else if (wid == 2) {
        // ========================= import warp =========================
        if (w > 0) {
            int dpc = 0;
            unsigned gf = 0;
            for (int kk = 0; kk < NBATCH; ++kk) {
                const int n0 = kk * GB;
                if (dpc < n0 - 24) { do { dpc = (int)sld_acq(&sm_dpc); } while (dpc < n0 - 24); }
                const unsigned need = (unsigned)(n0 + GB);
                while (gf < need) {
                    gf = ld_acq_g(&g_flag[w - 1]);
                    if (gf < need) __nanosleep(64);
                }
                float4 v = __ldcg((const float4*)&g_bnd[w - 1][n0][0] + lane);
                *((float4*)&sm_bnd[(n0 & 31) << 4] + lane) = v;
                __syncwarp();
                if (lane == 0) sst_rel(&sm_bctr, (unsigned)(n0 + GB));
            }
            if (lane == 0) sst_rel(&sm_bctr, 0x7ffffff0u);
        }
    }
    else {
        // ========================= export warp =========================
        int dpc = 0;
        for (int kk = 0; kk < NBATCH; ++kk) {
            const int b0 = kk * GB;
            const int need = b0 + 40;          // lane31 done block b0+7 at step b0+38
            if (dpc < need) { do { dpc = (int)sld_acq(&sm_dpc); } while (dpc < need); }
            float4 v = *((const float4*)&sm_exp[(b0 & 31) << 4] + lane);
            if (w == NCTA - 1) {
                ((float4*)(out + (b0 << 4)))[lane] = v;
            } else {
                __stcg((float4*)&g_bnd[w][b0][0] + lane, v);
            }
            __syncwarp();
            if (lane == 0) {
                if (w < NCTA - 1) st_rel_g(&g_flag[w], (unsigned)(b0 + GB));
                sst_rel(&sm_ectr, (unsigned)(b0 + GB));
            }
        }
    }
}

extern "C" void kernel_launch(void* const* d_in, const int* in_sizes, int n_in,
                              void* d_out, int out_size)
{
    const float* x;
    const float* ker;
    if (n_in >= 2 && in_sizes[0] == KLEN && in_sizes[1] != KLEN) {
        ker = (const float*)d_in[0];
        x   = (const float*)d_in[1];
    } else {
        x   = (const float*)d_in[0];
        ker = (const float*)d_in[1];
    }
    float* out = (float*)d_out;

    dtw_ws4_kernel<<<NCTA, 128>>>(x, ker, out);
}